// round 11
// baseline (speedup 1.0000x reference)
#include <cuda_runtime.h>
#include <math_constants.h>
#include <cstdint>

// ============================================================================
// Exact k-NN, fp32 throughout: coarse scan on packed fma.rn.f32x2 (FFMA2,
// 2 MACs/instr) + exact rescore.
//   1) bsq:     |b|^2 per base row
//   2) coarse:  thread-per-query f32x2 scan, per-thread EXACT top-10/chunk
//               on key = |b|^2 - 2*dot   (global top-10 provably covered)
//   3) merge:   37 chunk lists -> global top-32 per query
//   4) rescore: exact fp32 d2 of 32 candidates, sort, emit top-k
// R11 = R10 resubmit (container infra failure, kernel never ran).
// R10: FFMA/mma.sync/dp4a all measured at the same ~11.5 TMAC/s scalar wall;
//      f32x2 is the only remaining base-PTX 2x-rate MAC path (PTX ISA: sm_100+).
// ============================================================================

#define D128  128
#define NC    37        // base chunks
#define TB    32        // base rows per smem tile
#define KCC   10        // candidates per (query, chunk) — exact coverage
#define KG    32        // global coarse candidates per query
#define MAXN  262144
#define MAXQ  1024

__device__ float g_bsq[MAXN];
__device__ float g_ckey[NC * KCC * MAXQ];
__device__ int   g_cidx[NC * KCC * MAXQ];
__device__ int   g_sel [MAXQ * KG];

typedef unsigned long long ull;

__device__ __forceinline__ void fma2(ull& d, ull a, ull b) {
    asm("fma.rn.f32x2 %0, %1, %2, %0;" : "+l"(d) : "l"(a), "l"(b));
}
__device__ __forceinline__ float2 unpack2(ull v) {
    float2 r;
    asm("mov.b64 {%0, %1}, %2;" : "=f"(r.x), "=f"(r.y) : "l"(v));
    return r;
}

template<int K> __device__ __forceinline__
void topk_insert(float (&td)[K], int (&ti)[K], float& kmax, float v, int idx) {
    bool done = false;
    #pragma unroll
    for (int s = 0; s < K; ++s)
        if (!done && td[s] == kmax) { td[s] = v; ti[s] = idx; done = true; }
    float m = td[0];
    #pragma unroll
    for (int s = 1; s < K; ++s) m = fmaxf(m, td[s]);
    kmax = m;
}

// ---------------------------------------------------------------------------
// |row|^2, one warp per row.
// ---------------------------------------------------------------------------
__global__ void bsq_kernel(const float* __restrict__ src,
                           float* __restrict__ sq, int N) {
    int row = blockIdx.x * 8 + (threadIdx.x >> 5);
    if (row >= N) return;
    int lane = threadIdx.x & 31;
    float4 v = reinterpret_cast<const float4*>(src)[(size_t)row * 32 + lane];
    float s = v.x * v.x + v.y * v.y + v.z * v.z + v.w * v.w;
    #pragma unroll
    for (int off = 16; off > 0; off >>= 1) s += __shfl_xor_sync(0xFFFFFFFFu, s, off);
    if (lane == 0) sq[row] = s;
}

// ---------------------------------------------------------------------------
// Coarse scan: grid (NC, Q/256), block 256, 1 thread = 1 query.
// Query row (64 f32x2) in registers; 32-row fp32 base tiles in smem
// (broadcast LDS.128 as ulonglong2), reg-prefetch double buffer,
// 1 barrier/tile. 2-row groups, 8 independent f32x2 chains.
// ---------------------------------------------------------------------------
__global__ void __launch_bounds__(256)
knn_coarse_f2(const float* __restrict__ base,
              const float* __restrict__ query,
              int N, int Q) {
    __shared__ __align__(16) float sB[2][TB * D128];   // 2 x 16 KB
    __shared__ float sBsq[2][TB];

    const int tid   = threadIdx.x;
    const int chunk = blockIdx.x;
    const int qt    = blockIdx.y;

    const int chunk_len = (N + NC - 1) / NC;
    const int cs = chunk * chunk_len;
    const int ce = min(cs + chunk_len, N);
    const int ntiles = (ce - cs + TB - 1) / TB;

    const float4* base4 = reinterpret_cast<const float4*>(base);

    // query row -> 64 packed f32x2 registers
    ull qq[64];
    {
        int q = min(qt * 256 + tid, Q - 1);
        const ulonglong2* qrow =
            reinterpret_cast<const ulonglong2*>(query + (size_t)q * D128);
        #pragma unroll
        for (int i = 0; i < 32; ++i) {
            ulonglong2 u = qrow[i];
            qq[2 * i] = u.x; qq[2 * i + 1] = u.y;
        }
    }

    float td[KCC]; int ti[KCC];
    #pragma unroll
    for (int j = 0; j < KCC; ++j) { td[j] = CUDART_INF_F; ti[j] = -1; }
    float kmax = CUDART_INF_F;

    // prologue: tile 0 -> buffer 0  (tile = 32 rows x 32 float4 = 1024 float4)
    {
        #pragma unroll
        for (int j = 0; j < 4; ++j) {
            int c = tid + j * 256;          // 0..1023
            int row = c >> 5, ch = c & 31;
            int gr = min(cs + row, N - 1);
            reinterpret_cast<float4*>(&sB[0][0])[c] = base4[(size_t)gr * 32 + ch];
        }
        if (tid < TB) {
            int gr = cs + tid;
            sBsq[0][tid] = (gr < ce) ? g_bsq[gr] : CUDART_INF_F;
        }
        __syncthreads();
    }

    for (int t = 0; t < ntiles; ++t) {
        const int s = t & 1;
        const int n0 = cs + t * TB;
        const bool pf = (t + 1 < ntiles);

        // prefetch t+1 into registers (lands during fma phase)
        float4 r0, r1, r2, r3; float rb = CUDART_INF_F;
        if (pf) {
            const int n0n = n0 + TB;
            { int c = tid;       int row = c >> 5, ch = c & 31;
              r0 = base4[(size_t)min(n0n + row, N - 1) * 32 + ch]; }
            { int c = tid + 256; int row = c >> 5, ch = c & 31;
              r1 = base4[(size_t)min(n0n + row, N - 1) * 32 + ch]; }
            { int c = tid + 512; int row = c >> 5, ch = c & 31;
              r2 = base4[(size_t)min(n0n + row, N - 1) * 32 + ch]; }
            { int c = tid + 768; int row = c >> 5, ch = c & 31;
              r3 = base4[(size_t)min(n0n + row, N - 1) * 32 + ch]; }
            if (tid < TB) {
                int gr = n0n + tid;
                rb = (gr < ce) ? g_bsq[gr] : CUDART_INF_F;
            }
        }

        // scan 32 rows in 2-row groups: 64 LDS.128 + 128 f32x2 per group.
        // Out-of-range rows carry sBsq = +INF -> key = +INF -> never inserted.
        #pragma unroll 1
        for (int r = 0; r < TB; r += 2) {
            const ulonglong2* b0 =
                reinterpret_cast<const ulonglong2*>(&sB[s][r * D128]);
            const ulonglong2* b1 =
                reinterpret_cast<const ulonglong2*>(&sB[s][(r + 1) * D128]);
            ull d00 = 0ull, d01 = 0ull, d10 = 0ull, d11 = 0ull;
            #pragma unroll
            for (int i = 0; i < 32; ++i) {
                ulonglong2 x0 = b0[i];
                ulonglong2 x1 = b1[i];
                fma2(d00, qq[2 * i],     x0.x);
                fma2(d01, qq[2 * i + 1], x0.y);
                fma2(d10, qq[2 * i],     x1.x);
                fma2(d11, qq[2 * i + 1], x1.y);
            }
            float2 e00 = unpack2(d00), e01 = unpack2(d01);
            float2 e10 = unpack2(d10), e11 = unpack2(d11);
            float dot0 = (e00.x + e00.y) + (e01.x + e01.y);
            float dot1 = (e10.x + e10.y) + (e11.x + e11.y);
            float key0 = fmaf(-2.0f, dot0, sBsq[s][r]);
            float key1 = fmaf(-2.0f, dot1, sBsq[s][r + 1]);
            if (key0 < kmax) topk_insert(td, ti, kmax, key0, n0 + r);
            if (key1 < kmax) topk_insert(td, ti, kmax, key1, n0 + r + 1);
        }

        // store prefetched tile into other buffer, single barrier
        if (pf) {
            const int s1 = s ^ 1;
            reinterpret_cast<float4*>(&sB[s1][0])[tid]       = r0;
            reinterpret_cast<float4*>(&sB[s1][0])[tid + 256] = r1;
            reinterpret_cast<float4*>(&sB[s1][0])[tid + 512] = r2;
            reinterpret_cast<float4*>(&sB[s1][0])[tid + 768] = r3;
            if (tid < TB) sBsq[s1][tid] = rb;
        }
        __syncthreads();
    }

    // write candidates (transposed layout for coalesced merge reads)
    int q = qt * 256 + tid;
    if (q < Q) {
        #pragma unroll
        for (int j = 0; j < KCC; ++j) {
            g_ckey[(chunk * KCC + j) * MAXQ + q] = td[j];
            g_cidx[(chunk * KCC + j) * MAXQ + q] = ti[j];
        }
    }
}

// ---------------------------------------------------------------------------
// Merge NC*KCC chunk candidates -> global top-32 per query
// ---------------------------------------------------------------------------
__global__ void merge_kernel(int Q) {
    int q = blockIdx.x * blockDim.x + threadIdx.x;
    if (q >= Q) return;
    float td[KG]; int ti[KG];
    #pragma unroll
    for (int j = 0; j < KG; ++j) { td[j] = CUDART_INF_F; ti[j] = -1; }
    float kmax = CUDART_INF_F;
    for (int j = 0; j < NC * KCC; ++j) {
        float v = g_ckey[j * MAXQ + q];
        if (v < kmax) topk_insert(td, ti, kmax, v, g_cidx[j * MAXQ + q]);
    }
    #pragma unroll
    for (int j = 0; j < KG; ++j) g_sel[q * KG + j] = ti[j];
}

// ---------------------------------------------------------------------------
// Exact fp32 rescore of 32 candidates/query + final sort + output.
// 1 warp per query, lane = candidate.
// ---------------------------------------------------------------------------
__global__ void rescore_kernel(const float* __restrict__ base,
                               const float* __restrict__ query,
                               float* __restrict__ out, int N, int Q, int K) {
    __shared__ float sD[4][KG];
    __shared__ int   sI[4][KG];
    int w = threadIdx.x >> 5;
    int lane = threadIdx.x & 31;
    int q = blockIdx.x * 4 + w;
    if (q >= Q) return;

    int cand = g_sel[q * KG + lane];
    float d2;
    if (cand >= 0) {
        const float4* qrow = reinterpret_cast<const float4*>(query) + (size_t)q * 32;
        const float4* brow = reinterpret_cast<const float4*>(base) + (size_t)cand * 32;
        float dot = 0.f, qsq = 0.f;
        #pragma unroll
        for (int j = 0; j < 32; ++j) {
            float4 a = qrow[j], b = brow[j];
            dot += a.x * b.x + a.y * b.y + a.z * b.z + a.w * b.w;
            qsq += a.x * a.x + a.y * a.y + a.z * a.z + a.w * a.w;
        }
        d2 = qsq - 2.0f * dot + g_bsq[cand];
    } else {
        d2 = CUDART_INF_F; cand = 0x7fffffff;
    }
    sD[w][lane] = d2; sI[w][lane] = cand;
    __syncwarp();

    if (lane == 0) {
        float a[KG]; int b[KG];
        #pragma unroll
        for (int j = 0; j < KG; ++j) { a[j] = sD[w][j]; b[j] = sI[w][j]; }
        for (int r = 0; r < K; ++r) {
            int best = r;
            for (int j = r + 1; j < KG; ++j)
                if (a[j] < a[best] || (a[j] == a[best] && b[j] < b[best])) best = j;
            float tv = a[r]; a[r] = a[best]; a[best] = tv;
            int   ts = b[r]; b[r] = b[best]; b[best] = ts;
            out[(size_t)q * K + r]                 = (float)b[r];
            out[(size_t)Q * K + (size_t)q * K + r] = sqrtf(fmaxf(a[r], 0.0f));
        }
    }
}

// ---------------------------------------------------------------------------
extern "C" void kernel_launch(void* const* d_in, const int* in_sizes, int n_in,
                              void* d_out, int out_size) {
    const float* base  = (const float*)d_in[0];
    const float* query = (const float*)d_in[1];

    int N = in_sizes[0] / D128;
    int Q = in_sizes[1] / D128;
    int K = (Q > 0) ? out_size / (2 * Q) : 10;
    if (K <= 0 || K > KG) K = 10;

    float* bsq; cudaGetSymbolAddress((void**)&bsq, g_bsq);

    bsq_kernel<<<(N + 7) / 8, 256>>>(base, bsq, N);

    dim3 grid(NC, (Q + 255) / 256);
    knn_coarse_f2<<<grid, 256>>>(base, query, N, Q);

    merge_kernel<<<(Q + 255) / 256, 256>>>(Q);
    rescore_kernel<<<(Q + 3) / 4, 128>>>(base, query, (float*)d_out, N, Q, K);
}